// round 5
// baseline (speedup 1.0000x reference)
#include <cuda_runtime.h>
#include <cstring>

#define NT     256
#define ROWS   8
#define IT     4
#define JSPLIT 2

typedef unsigned long long u64;

__device__ double       g_sum;   // zero-init; reset by last block each run
__device__ double       g_adj;
__device__ unsigned int g_cnt;   // monotonic arrival counter (mod gridsize)

static __device__ __forceinline__ float sqa(float x) {
    float y; asm("sqrt.approx.f32 %0,%1;" : "=f"(y) : "f"(x)); return y;
}
static __device__ __forceinline__ u64 add2(u64 a, u64 b) {
    u64 d; asm("add.rn.f32x2 %0,%1,%2;" : "=l"(d) : "l"(a), "l"(b)); return d;
}

extern __shared__ float s_raw[];   // 8 SoA arrays of NH floats (conflict-free LDS.128)

__global__ void __launch_bounds__(NT, 4)
loss_kernel(const float* __restrict__ preds,
            const float* __restrict__ targets,
            const float* __restrict__ adj,
            float* __restrict__ out,
            int N)
{
    const int b    = blockIdx.z;
    const int jh   = blockIdx.y;
    const int row0 = blockIdx.x * ROWS;
    const int NH   = N / JSPLIT;
    const int j0   = jh * NH;

    float* spx = s_raw;           float* spy = spx + NH;
    float* spz = spy + NH;        float* spw = spz + NH;
    float* stx = spw + NH;        float* sty = stx + NH;
    float* stz = sty + NH;        float* stw = stz + NH;

    // Stage this CTA's j-half of points + squared norms into SMEM (SoA, 32KB)
    {
        const float* pb = preds   + ((size_t)b * N + j0) * 3;
        const float* tb = targets + ((size_t)b * N + j0) * 3;
        for (int k = threadIdx.x; k < NH; k += NT) {
            float x = pb[3*k], y = pb[3*k+1], z = pb[3*k+2];
            spx[k] = x; spy[k] = y; spz[k] = z; spw[k] = fmaf(x, x, fmaf(y, y, z*z));
            float u = tb[3*k], v = tb[3*k+1], w = tb[3*k+2];
            stx[k] = u; sty[k] = v; stz[k] = w; stw[k] = fmaf(u, u, fmaf(v, v, w*w));
        }
    }
    __syncthreads();

    float acc = 0.f;
    u64   accA2 = 0ull;                      // packed (0.f,0.f)
    const int NH4 = NH >> 2;
    const int N4  = N >> 2;
    const float* adjB = adj + (size_t)b * N * N;

    for (int ig = 0; ig < ROWS; ig += IT) {
        const int rbase = row0 + ig;

        // Row constants from global (broadcast, L1-hit), pre-scaled by -2
        float4 P[IT], T[IT];
        #pragma unroll
        for (int r = 0; r < IT; r++) {
            const float* pr = preds   + ((size_t)b * N + rbase + r) * 3;
            const float* tr = targets + ((size_t)b * N + rbase + r) * 3;
            float x = pr[0], y = pr[1], z = pr[2];
            P[r] = make_float4(-2.f*x, -2.f*y, -2.f*z, fmaf(x, x, fmaf(y, y, z*z)));
            float u = tr[0], v = tr[1], w = tr[2];
            T[r] = make_float4(-2.f*u, -2.f*v, -2.f*w, fmaf(u, u, fmaf(v, v, w*w)));
        }

        const float4* adjR = (const float4*)(adjB + (size_t)rbase * N + j0);

        for (int jv = threadIdx.x; jv < NH4; jv += NT) {
            // SoA vector loads: lane stride 16B -> conflict-free LDS.128
            float4 jpx = ((const float4*)spx)[jv];
            float4 jpy = ((const float4*)spy)[jv];
            float4 jpz = ((const float4*)spz)[jv];
            float4 jpw = ((const float4*)spw)[jv];
            float4 jtx = ((const float4*)stx)[jv];
            float4 jty = ((const float4*)sty)[jv];
            float4 jtz = ((const float4*)stz)[jv];
            float4 jtw = ((const float4*)stw)[jv];
            const float px_[4] = {jpx.x, jpx.y, jpx.z, jpx.w};
            const float py_[4] = {jpy.x, jpy.y, jpy.z, jpy.w};
            const float pz_[4] = {jpz.x, jpz.y, jpz.z, jpz.w};
            const float pw_[4] = {jpw.x, jpw.y, jpw.z, jpw.w};
            const float tx_[4] = {jtx.x, jtx.y, jtx.z, jtx.w};
            const float ty_[4] = {jty.x, jty.y, jty.z, jty.w};
            const float tz_[4] = {jtz.x, jtz.y, jtz.z, jtz.w};
            const float tw_[4] = {jtw.x, jtw.y, jtw.z, jtw.w};

            #pragma unroll
            for (int r = 0; r < IT; r++) {
                float4 a = __ldcs(adjR + (size_t)r * N4 + jv);
                float av[4] = {a.x, a.y, a.z, a.w};
                #pragma unroll
                for (int q = 0; q < 4; q++) {
                    float sqp = fmaf(P[r].x, px_[q],
                                fmaf(P[r].y, py_[q],
                                fmaf(P[r].z, pz_[q], P[r].w + pw_[q])));
                    float sqt = fmaf(T[r].x, tx_[q],
                                fmaf(T[r].y, ty_[q],
                                fmaf(T[r].z, tz_[q], T[r].w + tw_[q])));
                    // (sqrt(a)-sqrt(b))^2 = a + b - 2*sqrt(a*b): one MUFU/element
                    float rt = sqa(fmaxf(sqp * sqt, 0.f));
                    float d2 = fmaf(-2.f, rt, sqp + sqt);
                    acc = fmaf(d2, av[q], acc);   // adj in {0,1}
                }
                // packed adj-count: float4 quad is register-pair aligned -> free u64 view
                u64 a01, a23;
                memcpy(&a01, &a.x, 8);
                memcpy(&a23, &a.z, 8);
                accA2 = add2(accA2, a01);
                accA2 = add2(accA2, a23);
            }
        }
    }

    float nal, nah;
    memcpy(&nal, &accA2, 4);
    { unsigned int hi = (unsigned int)(accA2 >> 32); memcpy(&nah, &hi, 4); }
    float accA = nal + nah;

    // warp reduce
    #pragma unroll
    for (int off = 16; off > 0; off >>= 1) {
        acc  += __shfl_down_sync(0xffffffffu, acc,  off);
        accA += __shfl_down_sync(0xffffffffu, accA, off);
    }
    __shared__ float2 wsum[NT / 32];
    int wid = threadIdx.x >> 5, lane = threadIdx.x & 31;
    if (lane == 0) wsum[wid] = make_float2(acc, accA);
    __syncthreads();
    if (wid == 0) {
        float2 v = (lane < NT / 32) ? wsum[lane] : make_float2(0.f, 0.f);
        #pragma unroll
        for (int off = 4; off > 0; off >>= 1) {
            v.x += __shfl_down_sync(0xffffffffu, v.x, off);
            v.y += __shfl_down_sync(0xffffffffu, v.y, off);
        }
        if (lane == 0) {
            atomicAdd(&g_sum, (double)v.x);
            atomicAdd(&g_adj, (double)v.y);
            __threadfence();
            unsigned int nb  = gridDim.x * gridDim.y * gridDim.z;
            unsigned int old = atomicAdd(&g_cnt, 1u);
            if (old % nb == nb - 1u) {            // last block of this run
                __threadfence();
                double s = atomicAdd(&g_sum, 0.0);
                double n = atomicAdd(&g_adj, 0.0);
                out[0] = (float)(s / n);
                g_sum = 0.0;                       // reset for next graph replay
                g_adj = 0.0;
            }
        }
    }
}

extern "C" void kernel_launch(void* const* d_in, const int* in_sizes, int n_in,
                              void* d_out, int out_size)
{
    const float* preds   = (const float*)d_in[0];
    const float* targets = (const float*)d_in[1];
    const float* adj     = (const float*)d_in[2];

    long long psz   = in_sizes[0];          // B*N*3
    long long adjsz = in_sizes[2];          // B*N*N
    int N = (int)(3LL * adjsz / psz);       // 2048
    int B = (int)(psz / (3LL * N));         // 8

    size_t smem = (size_t)8 * (N / JSPLIT) * sizeof(float);  // 32KB
    cudaFuncSetAttribute(loss_kernel, cudaFuncAttributeMaxDynamicSharedMemorySize, (int)smem);

    dim3 grid(N / ROWS, JSPLIT, B);
    loss_kernel<<<grid, NT, smem>>>(preds, targets, adj, (float*)d_out, N);
}

// round 6
// speedup vs baseline: 1.7071x; 1.7071x over previous
#include <cuda_runtime.h>

#define NT     256
#define ROWS   16
#define IT     4

__device__ double       g_sum;   // zero-init; reset by last block each run
__device__ double       g_adj;
__device__ unsigned int g_cnt;   // monotonic arrival counter (mod gridsize)

static __device__ __forceinline__ float sqa(float x) {
    float y; asm("sqrt.approx.f32 %0,%1;" : "=f"(y) : "f"(x)); return y;
}

extern __shared__ float s_raw[];   // 8 SoA arrays of N floats (conflict-free LDS.128)

__global__ void __launch_bounds__(NT, 2)
loss_kernel(const float* __restrict__ preds,
            const float* __restrict__ targets,
            const float* __restrict__ adj,
            float* __restrict__ out,
            int N)
{
    const int b    = blockIdx.y;
    const int row0 = blockIdx.x * ROWS;

    float* spx = s_raw;          float* spy = spx + N;
    float* spz = spy + N;        float* spw = spz + N;
    float* stx = spw + N;        float* sty = stx + N;
    float* stz = sty + N;        float* stw = stz + N;

    // Stage all N points + squared norms into SMEM (SoA, 64KB)
    {
        const float* pb = preds   + (size_t)b * N * 3;
        const float* tb = targets + (size_t)b * N * 3;
        for (int k = threadIdx.x; k < N; k += NT) {
            float x = pb[3*k], y = pb[3*k+1], z = pb[3*k+2];
            spx[k] = x; spy[k] = y; spz[k] = z; spw[k] = fmaf(x, x, fmaf(y, y, z*z));
            float u = tb[3*k], v = tb[3*k+1], w = tb[3*k+2];
            stx[k] = u; sty[k] = v; stz[k] = w; stw[k] = fmaf(u, u, fmaf(v, v, w*w));
        }
    }
    __syncthreads();

    float acc = 0.f, accA = 0.f;
    const int N4 = N >> 2;
    const float* adjB = adj + (size_t)b * N * N;

    for (int ig = 0; ig < ROWS; ig += IT) {
        const int rbase = row0 + ig;

        // Row constants from SMEM (broadcast LDS), pre-scaled by -2
        float4 P[IT], T[IT];
        #pragma unroll
        for (int r = 0; r < IT; r++) {
            int k = rbase + r;
            P[r] = make_float4(-2.f*spx[k], -2.f*spy[k], -2.f*spz[k], spw[k]);
            T[r] = make_float4(-2.f*stx[k], -2.f*sty[k], -2.f*stz[k], stw[k]);
        }

        const float4* adjR = (const float4*)(adjB + (size_t)rbase * N);

        for (int jv = threadIdx.x; jv < N4; jv += NT) {
            // SoA vector loads: lane stride 16B -> conflict-free LDS.128
            float4 jpx = ((const float4*)spx)[jv];
            float4 jpy = ((const float4*)spy)[jv];
            float4 jpz = ((const float4*)spz)[jv];
            float4 jpw = ((const float4*)spw)[jv];
            float4 jtx = ((const float4*)stx)[jv];
            float4 jty = ((const float4*)sty)[jv];
            float4 jtz = ((const float4*)stz)[jv];
            float4 jtw = ((const float4*)stw)[jv];
            const float px_[4] = {jpx.x, jpx.y, jpx.z, jpx.w};
            const float py_[4] = {jpy.x, jpy.y, jpy.z, jpy.w};
            const float pz_[4] = {jpz.x, jpz.y, jpz.z, jpz.w};
            const float pw_[4] = {jpw.x, jpw.y, jpw.z, jpw.w};
            const float tx_[4] = {jtx.x, jtx.y, jtx.z, jtx.w};
            const float ty_[4] = {jty.x, jty.y, jty.z, jty.w};
            const float tz_[4] = {jtz.x, jtz.y, jtz.z, jtz.w};
            const float tw_[4] = {jtw.x, jtw.y, jtw.z, jtw.w};

            #pragma unroll
            for (int r = 0; r < IT; r++) {
                float4 a = adjR[(size_t)r * N4 + jv];
                float av[4] = {a.x, a.y, a.z, a.w};
                #pragma unroll
                for (int q = 0; q < 4; q++) {
                    float sqp = fmaf(P[r].x, px_[q],
                                fmaf(P[r].y, py_[q],
                                fmaf(P[r].z, pz_[q], P[r].w + pw_[q])));
                    float sqt = fmaf(T[r].x, tx_[q],
                                fmaf(T[r].y, ty_[q],
                                fmaf(T[r].z, tz_[q], T[r].w + tw_[q])));
                    // (sqrt(a)-sqrt(b))^2 = a + b - 2*sqrt(a*b): one MUFU/element
                    float rt = sqa(fmaxf(sqp * sqt, 0.f));
                    float d2 = fmaf(-2.f, rt, sqp + sqt);
                    acc = fmaf(d2, av[q], acc);   // adj in {0,1}
                }
                accA += (a.x + a.y) + (a.z + a.w);
            }
        }
    }

    // warp reduce
    #pragma unroll
    for (int off = 16; off > 0; off >>= 1) {
        acc  += __shfl_down_sync(0xffffffffu, acc,  off);
        accA += __shfl_down_sync(0xffffffffu, accA, off);
    }
    __shared__ float2 wsum[NT / 32];
    int wid = threadIdx.x >> 5, lane = threadIdx.x & 31;
    if (lane == 0) wsum[wid] = make_float2(acc, accA);
    __syncthreads();
    if (wid == 0) {
        float2 v = (lane < NT / 32) ? wsum[lane] : make_float2(0.f, 0.f);
        #pragma unroll
        for (int off = 4; off > 0; off >>= 1) {
            v.x += __shfl_down_sync(0xffffffffu, v.x, off);
            v.y += __shfl_down_sync(0xffffffffu, v.y, off);
        }
        if (lane == 0) {
            atomicAdd(&g_sum, (double)v.x);
            atomicAdd(&g_adj, (double)v.y);
            __threadfence();
            unsigned int nb  = gridDim.x * gridDim.y;
            unsigned int old = atomicAdd(&g_cnt, 1u);
            if (old % nb == nb - 1u) {            // last block of this run
                __threadfence();
                double s = atomicAdd(&g_sum, 0.0);
                double n = atomicAdd(&g_adj, 0.0);
                out[0] = (float)(s / n);
                g_sum = 0.0;                       // reset for next graph replay
                g_adj = 0.0;
            }
        }
    }
}

extern "C" void kernel_launch(void* const* d_in, const int* in_sizes, int n_in,
                              void* d_out, int out_size)
{
    const float* preds   = (const float*)d_in[0];
    const float* targets = (const float*)d_in[1];
    const float* adj     = (const float*)d_in[2];

    long long psz   = in_sizes[0];          // B*N*3
    long long adjsz = in_sizes[2];          // B*N*N
    int N = (int)(3LL * adjsz / psz);       // 2048
    int B = (int)(psz / (3LL * N));         // 8

    size_t smem = (size_t)8 * N * sizeof(float);  // 64KB
    cudaFuncSetAttribute(loss_kernel, cudaFuncAttributeMaxDynamicSharedMemorySize, (int)smem);

    dim3 grid(N / ROWS, B);
    loss_kernel<<<grid, NT, smem>>>(preds, targets, adj, (float*)d_out, N);
}